// round 5
// baseline (speedup 1.0000x reference)
#include <cuda_runtime.h>
#include <math.h>

// Problem constants (StatsSelect: B=32, C=512, T=4000, BR=2)
#define BB   32
#define CC   512
#define TT   4000
#define H4   2048          // 4*C stats features
#define NROW (BB * CC)     // 16384 rows
#define T4   (TT / 4)      // 1000 float4 per row

// Scratch (no cudaMalloc allowed)
__device__ float g_stats[BB * H4];   // [B, 4C]: mean | std | skew | kurt
__device__ float g_h[BB * CC];       // hidden   [B, C]
__device__ float g_gate[BB * CC];    // softmax gate for branch 0, per (b,c)

// ---------------------------------------------------------------------------
// Kernel 1: per-row raw moments of (x_a + x_b) over T, then HOS stats.
// One block per (b,c) row. 256 threads, float4 loads. HBM-bound: 524 MB read.
// ---------------------------------------------------------------------------
__global__ __launch_bounds__(256) void k_stats(const float* __restrict__ xa,
                                               const float* __restrict__ xb)
{
    const int row = blockIdx.x;
    const float4* a4 = reinterpret_cast<const float4*>(xa) + (size_t)row * T4;
    const float4* b4 = reinterpret_cast<const float4*>(xb) + (size_t)row * T4;

    float s1 = 0.f, s2 = 0.f, s3 = 0.f, s4 = 0.f;
    for (int i = threadIdx.x; i < T4; i += 256) {
        float4 a = a4[i];
        float4 b = b4[i];
        float v, v2;
        v = a.x + b.x; v2 = v * v; s1 += v; s2 += v2; s3 += v2 * v; s4 += v2 * v2;
        v = a.y + b.y; v2 = v * v; s1 += v; s2 += v2; s3 += v2 * v; s4 += v2 * v2;
        v = a.z + b.z; v2 = v * v; s1 += v; s2 += v2; s3 += v2 * v; s4 += v2 * v2;
        v = a.w + b.w; v2 = v * v; s1 += v; s2 += v2; s3 += v2 * v; s4 += v2 * v2;
    }

    #pragma unroll
    for (int off = 16; off; off >>= 1) {
        s1 += __shfl_xor_sync(0xffffffffu, s1, off);
        s2 += __shfl_xor_sync(0xffffffffu, s2, off);
        s3 += __shfl_xor_sync(0xffffffffu, s3, off);
        s4 += __shfl_xor_sync(0xffffffffu, s4, off);
    }

    __shared__ float4 sm[8];
    const int lane = threadIdx.x & 31, wid = threadIdx.x >> 5;
    if (lane == 0) sm[wid] = make_float4(s1, s2, s3, s4);
    __syncthreads();

    if (threadIdx.x == 0) {
        float S1 = 0.f, S2 = 0.f, S3 = 0.f, S4 = 0.f;
        #pragma unroll
        for (int w = 0; w < 8; w++) {
            float4 v = sm[w];
            S1 += v.x; S2 += v.y; S3 += v.z; S4 += v.w;
        }
        const float invT = 1.0f / (float)TT;
        const float mean = S1 * invT;
        const float ex2  = S2 * invT;
        const float ex3  = S3 * invT;
        const float ex4  = S4 * invT;
        // unbiased variance: (S2 - T*mean^2) / (T-1); S1*mean == T*mean^2
        const float var  = (S2 - S1 * mean) * (1.0f / (float)(TT - 1));
        const float stdv = sqrtf(fmaxf(var, 0.0f));
        const float d    = fmaxf(stdv, 0.01f);   // EPS
        const float m3 = ex3 - 3.0f * mean * ex2 + 2.0f * mean * mean * mean;
        const float m4 = ex4 - 4.0f * mean * ex3 + 6.0f * mean * mean * ex2
                         - 3.0f * mean * mean * mean * mean;
        const float id  = 1.0f / d;
        const float id2 = id * id;

        const int b = row >> 9;       // row / C
        const int c = row & (CC - 1); // row % C
        float* s = g_stats + b * H4;
        s[c]           = mean;
        s[CC + c]      = stdv;
        s[2 * CC + c]  = m3 * id2 * id;
        s[3 * CC + c]  = m4 * id2 * id2;
    }
}

// ---------------------------------------------------------------------------
// Kernel 2a: h[b,o] = stats[b,:] . W1[o,:] + b1[o].  Grid = 512 blocks (one
// per o). W1 row cached in shared; 8 warps each handle 4 batches with lanes
// striding the 2048-dim contraction (coalesced stats reads, shuffle reduce).
// ---------------------------------------------------------------------------
__global__ __launch_bounds__(256) void k_h(const float* __restrict__ W1,
                                           const float* __restrict__ b1)
{
    const int o = blockIdx.x;
    __shared__ float w[H4];
    for (int j = threadIdx.x; j < H4; j += 256)
        w[j] = W1[(size_t)o * H4 + j];
    __syncthreads();

    const int lane = threadIdx.x & 31, wid = threadIdx.x >> 5;  // 8 warps
    const float bias = b1[o];

    for (int b = wid; b < BB; b += 8) {
        const float* sp = g_stats + b * H4;
        float acc = 0.f;
        for (int j = lane; j < H4; j += 32)
            acc = fmaf(sp[j], w[j], acc);
        #pragma unroll
        for (int off = 16; off; off >>= 1)
            acc += __shfl_xor_sync(0xffffffffu, acc, off);
        if (lane == 0)
            g_h[b * CC + o] = acc + bias;
    }
}

// ---------------------------------------------------------------------------
// Kernel 2b: s[b,k,o] = h[b,:] . W2[k,o,:] + b2[k,o]; gate = sigmoid(s0-s1).
// Grid = 32 blocks (one per b). h row in shared; each warp owns channels o
// with lanes striding the 512-dim contraction (coalesced W2 reads).
// ---------------------------------------------------------------------------
__global__ __launch_bounds__(512) void k_gate(const float* __restrict__ W2,
                                              const float* __restrict__ b2)
{
    const int b = blockIdx.x;
    __shared__ float hv[CC];
    for (int j = threadIdx.x; j < CC; j += 512)
        hv[j] = g_h[b * CC + j];
    __syncthreads();

    const int lane = threadIdx.x & 31, wid = threadIdx.x >> 5;  // 16 warps

    for (int o = wid; o < CC; o += 16) {
        const float* w0 = W2 + (size_t)o * CC;                   // k=0
        const float* w1 = W2 + (size_t)CC * CC + (size_t)o * CC; // k=1
        float a0 = 0.f, a1 = 0.f;
        for (int h = lane; h < CC; h += 32) {
            const float hh = hv[h];
            a0 = fmaf(hh, w0[h], a0);
            a1 = fmaf(hh, w1[h], a1);
        }
        #pragma unroll
        for (int off = 16; off; off >>= 1) {
            a0 += __shfl_xor_sync(0xffffffffu, a0, off);
            a1 += __shfl_xor_sync(0xffffffffu, a1, off);
        }
        if (lane == 0) {
            const float s0 = a0 + b2[o];
            const float s1 = a1 + b2[CC + o];
            // softmax over 2 -> branch-0 weight = sigmoid(s0 - s1)
            g_gate[b * CC + o] = 1.0f / (1.0f + expf(s1 - s0));
        }
    }
}

// ---------------------------------------------------------------------------
// Kernel 3: out = g*x_a + (1-g)*x_b, per-row scalar gate. One block per row,
// float4 vectorized. HBM-bound: 524 MB read + 262 MB write.
// ---------------------------------------------------------------------------
__global__ __launch_bounds__(256) void k_out(const float* __restrict__ xa,
                                             const float* __restrict__ xb,
                                             float* __restrict__ out)
{
    const int row = blockIdx.x;
    const float g  = g_gate[row];
    const float g1 = 1.0f - g;

    const float4* a4 = reinterpret_cast<const float4*>(xa) + (size_t)row * T4;
    const float4* b4 = reinterpret_cast<const float4*>(xb) + (size_t)row * T4;
    float4*       o4 = reinterpret_cast<float4*>(out)      + (size_t)row * T4;

    for (int i = threadIdx.x; i < T4; i += 256) {
        const float4 a = a4[i];
        const float4 b = b4[i];
        float4 r;
        r.x = fmaf(g, a.x, g1 * b.x);
        r.y = fmaf(g, a.y, g1 * b.y);
        r.z = fmaf(g, a.z, g1 * b.z);
        r.w = fmaf(g, a.w, g1 * b.w);
        o4[i] = r;
    }
}

// ---------------------------------------------------------------------------
extern "C" void kernel_launch(void* const* d_in, const int* in_sizes, int n_in,
                              void* d_out, int out_size)
{
    const float* xa = (const float*)d_in[0];  // [B, C, T]
    const float* xb = (const float*)d_in[1];  // [B, C, T]
    const float* W1 = (const float*)d_in[2];  // [C, 4C]
    const float* b1 = (const float*)d_in[3];  // [C]
    const float* W2 = (const float*)d_in[4];  // [BR, C, C]
    const float* b2 = (const float*)d_in[5];  // [BR, C]
    float* out = (float*)d_out;               // [B, C, T]

    k_stats<<<NROW, 256>>>(xa, xb);
    k_h<<<CC, 256>>>(W1, b1);
    k_gate<<<BB, 512>>>(W2, b2);
    k_out<<<NROW, 256>>>(xa, xb, out);
}

// round 6
// speedup vs baseline: 1.0019x; 1.0019x over previous
#include <cuda_runtime.h>
#include <math.h>

// Problem constants (StatsSelect: B=32, C=512, T=4000, BR=2)
#define BB   32
#define CC   512
#define TT   4000
#define H4   2048          // 4*C stats features
#define NROW (BB * CC)     // 16384 rows
#define T4   (TT / 4)      // 1000 float4 per row

// Scratch (no cudaMalloc allowed)
__device__ float g_stats[BB * H4];   // [B, 4C]: mean | std | skew | kurt
__device__ float g_h[BB * CC];       // hidden   [B, C]
__device__ float g_gate[BB * CC];    // gate (branch-0 weight) per (b,c)

// ---------------------------------------------------------------------------
// Kernel 1: per-row raw moments of (x_a + x_b) over T, then HOS stats.
// One block per (b,c) row, 256 threads. All 8 LDG.128s per thread are issued
// UP FRONT (predicated, zero-filled past T4) so MLP_p1=8 -> 4KB in flight per
// warp, covering the ~577cyc DRAM latency. Then the FMA chains run on regs.
// ---------------------------------------------------------------------------
__global__ __launch_bounds__(256) void k_stats(const float* __restrict__ xa,
                                               const float* __restrict__ xb)
{
    const int row = blockIdx.x;
    const float4* a4 = reinterpret_cast<const float4*>(xa) + (size_t)row * T4;
    const float4* b4 = reinterpret_cast<const float4*>(xb) + (size_t)row * T4;

    // Batch-issue all loads first. T4=1000, 256 thr -> 4 strided positions.
    float4 av[4], bv[4];
    const float4 z4 = make_float4(0.f, 0.f, 0.f, 0.f);
    #pragma unroll
    for (int u = 0; u < 4; u++) {
        const int idx = threadIdx.x + u * 256;
        const bool ok = (idx < T4);
        av[u] = ok ? __ldg(a4 + idx) : z4;
        bv[u] = ok ? __ldg(b4 + idx) : z4;
    }

    float s1 = 0.f, s2 = 0.f, s3 = 0.f, s4 = 0.f;
    #pragma unroll
    for (int u = 0; u < 4; u++) {
        float v, v2;
        v = av[u].x + bv[u].x; v2 = v * v; s1 += v; s2 += v2; s3 += v2 * v; s4 += v2 * v2;
        v = av[u].y + bv[u].y; v2 = v * v; s1 += v; s2 += v2; s3 += v2 * v; s4 += v2 * v2;
        v = av[u].z + bv[u].z; v2 = v * v; s1 += v; s2 += v2; s3 += v2 * v; s4 += v2 * v2;
        v = av[u].w + bv[u].w; v2 = v * v; s1 += v; s2 += v2; s3 += v2 * v; s4 += v2 * v2;
    }

    #pragma unroll
    for (int off = 16; off; off >>= 1) {
        s1 += __shfl_xor_sync(0xffffffffu, s1, off);
        s2 += __shfl_xor_sync(0xffffffffu, s2, off);
        s3 += __shfl_xor_sync(0xffffffffu, s3, off);
        s4 += __shfl_xor_sync(0xffffffffu, s4, off);
    }

    __shared__ float4 sm[8];
    const int lane = threadIdx.x & 31, wid = threadIdx.x >> 5;
    if (lane == 0) sm[wid] = make_float4(s1, s2, s3, s4);
    __syncthreads();

    if (wid == 0) {
        // warp 0 finishes: lanes 0..7 hold partials, butterfly over 8 lanes
        float4 p = (lane < 8) ? sm[lane] : make_float4(0.f, 0.f, 0.f, 0.f);
        float S1 = p.x, S2 = p.y, S3 = p.z, S4 = p.w;
        #pragma unroll
        for (int off = 4; off; off >>= 1) {
            S1 += __shfl_xor_sync(0xffffffffu, S1, off);
            S2 += __shfl_xor_sync(0xffffffffu, S2, off);
            S3 += __shfl_xor_sync(0xffffffffu, S3, off);
            S4 += __shfl_xor_sync(0xffffffffu, S4, off);
        }
        if (lane == 0) {
            const float invT = 1.0f / (float)TT;
            const float mean = S1 * invT;
            const float ex2  = S2 * invT;
            const float ex3  = S3 * invT;
            const float ex4  = S4 * invT;
            const float var  = (S2 - S1 * mean) * (1.0f / (float)(TT - 1));
            const float stdv = sqrtf(fmaxf(var, 0.0f));
            const float d    = fmaxf(stdv, 0.01f);   // EPS
            const float m2   = mean * mean;
            const float m3 = ex3 - 3.0f * mean * ex2 + 2.0f * m2 * mean;
            const float m4 = ex4 - 4.0f * mean * ex3 + 6.0f * m2 * ex2
                             - 3.0f * m2 * m2;
            const float id  = 1.0f / d;
            const float id2 = id * id;

            const int b = row >> 9;       // row / C
            const int c = row & (CC - 1); // row % C
            float* s = g_stats + b * H4;
            s[c]           = mean;
            s[CC + c]      = stdv;
            s[2 * CC + c]  = m3 * id2 * id;
            s[3 * CC + c]  = m4 * id2 * id2;
        }
    }
}

// ---------------------------------------------------------------------------
// Kernel 2a: h[b,o] = stats[b,:] . W1[o,:] + b1[o].  One block per o.
// ---------------------------------------------------------------------------
__global__ __launch_bounds__(256) void k_h(const float* __restrict__ W1,
                                           const float* __restrict__ b1)
{
    const int o = blockIdx.x;
    __shared__ float w[H4];
    for (int j = threadIdx.x; j < H4; j += 256)
        w[j] = W1[(size_t)o * H4 + j];
    __syncthreads();

    const int lane = threadIdx.x & 31, wid = threadIdx.x >> 5;  // 8 warps
    const float bias = b1[o];

    for (int b = wid; b < BB; b += 8) {
        const float* sp = g_stats + b * H4;
        float acc = 0.f;
        #pragma unroll 4
        for (int j = lane; j < H4; j += 32)
            acc = fmaf(sp[j], w[j], acc);
        #pragma unroll
        for (int off = 16; off; off >>= 1)
            acc += __shfl_xor_sync(0xffffffffu, acc, off);
        if (lane == 0)
            g_h[b * CC + o] = acc + bias;
    }
}

// ---------------------------------------------------------------------------
// Kernel 2b: s[b,k,o] = h[b,:] . W2[k,o,:] + b2[k,o]; gate = sigmoid(s0-s1).
// One block per b; each warp owns channels o, lanes stride the contraction.
// ---------------------------------------------------------------------------
__global__ __launch_bounds__(512) void k_gate(const float* __restrict__ W2,
                                              const float* __restrict__ b2)
{
    const int b = blockIdx.x;
    __shared__ float hv[CC];
    for (int j = threadIdx.x; j < CC; j += 512)
        hv[j] = g_h[b * CC + j];
    __syncthreads();

    const int lane = threadIdx.x & 31, wid = threadIdx.x >> 5;  // 16 warps

    for (int o = wid; o < CC; o += 16) {
        const float* w0 = W2 + (size_t)o * CC;                   // k=0
        const float* w1 = W2 + (size_t)CC * CC + (size_t)o * CC; // k=1
        float a0 = 0.f, a1 = 0.f;
        #pragma unroll 4
        for (int h = lane; h < CC; h += 32) {
            const float hh = hv[h];
            a0 = fmaf(hh, w0[h], a0);
            a1 = fmaf(hh, w1[h], a1);
        }
        #pragma unroll
        for (int off = 16; off; off >>= 1) {
            a0 += __shfl_xor_sync(0xffffffffu, a0, off);
            a1 += __shfl_xor_sync(0xffffffffu, a1, off);
        }
        if (lane == 0) {
            const float s0 = a0 + b2[o];
            const float s1 = a1 + b2[CC + o];
            g_gate[b * CC + o] = 1.0f / (1.0f + expf(s1 - s0));
        }
    }
}

// ---------------------------------------------------------------------------
// Kernel 3: out = g*x_a + (1-g)*x_b. Already at 84.8% DRAM -> unchanged.
// ---------------------------------------------------------------------------
__global__ __launch_bounds__(256) void k_out(const float* __restrict__ xa,
                                             const float* __restrict__ xb,
                                             float* __restrict__ out)
{
    const int row = blockIdx.x;
    const float g  = g_gate[row];
    const float g1 = 1.0f - g;

    const float4* a4 = reinterpret_cast<const float4*>(xa) + (size_t)row * T4;
    const float4* b4 = reinterpret_cast<const float4*>(xb) + (size_t)row * T4;
    float4*       o4 = reinterpret_cast<float4*>(out)      + (size_t)row * T4;

    for (int i = threadIdx.x; i < T4; i += 256) {
        const float4 a = a4[i];
        const float4 b = b4[i];
        float4 r;
        r.x = fmaf(g, a.x, g1 * b.x);
        r.y = fmaf(g, a.y, g1 * b.y);
        r.z = fmaf(g, a.z, g1 * b.z);
        r.w = fmaf(g, a.w, g1 * b.w);
        o4[i] = r;
    }
}

// ---------------------------------------------------------------------------
extern "C" void kernel_launch(void* const* d_in, const int* in_sizes, int n_in,
                              void* d_out, int out_size)
{
    const float* xa = (const float*)d_in[0];  // [B, C, T]
    const float* xb = (const float*)d_in[1];  // [B, C, T]
    const float* W1 = (const float*)d_in[2];  // [C, 4C]
    const float* b1 = (const float*)d_in[3];  // [C]
    const float* W2 = (const float*)d_in[4];  // [BR, C, C]
    const float* b2 = (const float*)d_in[5];  // [BR, C]
    float* out = (float*)d_out;               // [B, C, T]

    k_stats<<<NROW, 256>>>(xa, xb);
    k_h<<<CC, 256>>>(W1, b1);
    k_gate<<<BB, 512>>>(W2, b2);
    k_out<<<NROW, 256>>>(xa, xb, out);
}